// round 2
// baseline (speedup 1.0000x reference)
#include <cuda_runtime.h>
#include <math.h>

#define BB 8
#define NN 1024
#define FF 512
#define HH 4
#define DD 128
#define ROWS (BB*NN)            // 8192
#define BH   (BB*HH)            // 32
#define LN_EPS 1e-5f
#define FLOATMAX 3.402823466e+38f

// ---------------- scratch (static device globals; no allocs allowed) ----------
__device__ float g_h[(size_t)ROWS*FF];                 // 16 MB: h = x @ W
__device__ float g_esrc[ROWS*HH];
__device__ float g_edst[ROWS*HH];
__device__ float g_key [BH*NN];                        // sorted e_dst keys per (b,h)
__device__ int   g_sidx[BH*NN];                        // sorted j indices
__device__ int   g_nvalid[BB];
__device__ float g_p1[(size_t)BH*(NN+1)*DD];           // prefix sums, 0.2-branch
__device__ float g_p2[(size_t)BH*(NN+1)*DD];           // prefix sums, 1.0-branch
__device__ float g_s1[BH*(NN+1)];
__device__ float g_s2[BH*(NN+1)];
__device__ float g_hmean[BH*DD];                       // mean over all j of h

// ---------------- kernel 1: SGEMM  g_h = x @ W  (8192x512x512, fp32) ----------
__global__ __launch_bounds__(256, 2)
void k_gemm(const float* __restrict__ A, const float* __restrict__ Bw)
{
    __shared__ float As[16][132];
    __shared__ float Bs[16][132];
    const int K = FF, Nc = FF;
    int tid = threadIdx.x;
    int rowBase = blockIdx.y * 128;
    int colBase = blockIdx.x * 128;
    int ty = tid >> 4, tx = tid & 15;

    float acc[8][8];
#pragma unroll
    for (int i = 0; i < 8; i++)
#pragma unroll
        for (int j = 0; j < 8; j++) acc[i][j] = 0.f;

    for (int k0 = 0; k0 < K; k0 += 16) {
#pragma unroll
        for (int l = 0; l < 2; l++) {
            int fid = tid + l * 256;
            int r  = fid >> 2;
            int kc = (fid & 3) << 2;
            float4 v = *reinterpret_cast<const float4*>(
                &A[(size_t)(rowBase + r) * K + k0 + kc]);
            As[kc + 0][r] = v.x; As[kc + 1][r] = v.y;
            As[kc + 2][r] = v.z; As[kc + 3][r] = v.w;
        }
#pragma unroll
        for (int l = 0; l < 2; l++) {
            int fid = tid + l * 256;
            int r  = fid >> 5;
            int c4 = (fid & 31) << 2;
            *reinterpret_cast<float4*>(&Bs[r][c4]) =
                *reinterpret_cast<const float4*>(
                    &Bw[(size_t)(k0 + r) * Nc + colBase + c4]);
        }
        __syncthreads();
#pragma unroll
        for (int kk = 0; kk < 16; kk++) {
            float4 a0 = *reinterpret_cast<const float4*>(&As[kk][ty * 8]);
            float4 a1 = *reinterpret_cast<const float4*>(&As[kk][ty * 8 + 4]);
            float4 b0 = *reinterpret_cast<const float4*>(&Bs[kk][tx * 8]);
            float4 b1 = *reinterpret_cast<const float4*>(&Bs[kk][tx * 8 + 4]);
            float ar[8] = {a0.x, a0.y, a0.z, a0.w, a1.x, a1.y, a1.z, a1.w};
            float br[8] = {b0.x, b0.y, b0.z, b0.w, b1.x, b1.y, b1.z, b1.w};
#pragma unroll
            for (int i = 0; i < 8; i++)
#pragma unroll
                for (int j = 0; j < 8; j++)
                    acc[i][j] = fmaf(ar[i], br[j], acc[i][j]);
        }
        __syncthreads();
    }
#pragma unroll
    for (int i = 0; i < 8; i++) {
        int r = rowBase + ty * 8 + i;
        float4 c0 = make_float4(acc[i][0], acc[i][1], acc[i][2], acc[i][3]);
        float4 c1 = make_float4(acc[i][4], acc[i][5], acc[i][6], acc[i][7]);
        *reinterpret_cast<float4*>(&g_h[(size_t)r * Nc + colBase + tx * 8])     = c0;
        *reinterpret_cast<float4*>(&g_h[(size_t)r * Nc + colBase + tx * 8 + 4]) = c1;
    }
}

// ---------------- kernel 2: e_src/e_dst = h . a_src / a_dst  (warp per row,head)
__global__ __launch_bounds__(256)
void k_eproj(const float* __restrict__ a_src, const float* __restrict__ a_dst)
{
    int gw   = (blockIdx.x * blockDim.x + threadIdx.x) >> 5;
    int lane = threadIdx.x & 31;
    if (gw >= ROWS * HH) return;
    int row = gw >> 2;
    int hh  = gw & 3;
    float4 hv = *reinterpret_cast<const float4*>(&g_h[(size_t)row * FF + hh * DD + lane * 4]);
    float4 as = *reinterpret_cast<const float4*>(&a_src[hh * DD + lane * 4]);
    float4 ad = *reinterpret_cast<const float4*>(&a_dst[hh * DD + lane * 4]);
    float s = hv.x * as.x + hv.y * as.y + hv.z * as.z + hv.w * as.w;
    float t = hv.x * ad.x + hv.y * ad.y + hv.z * ad.z + hv.w * ad.w;
#pragma unroll
    for (int o = 16; o > 0; o >>= 1) {
        s += __shfl_xor_sync(0xffffffffu, s, o);
        t += __shfl_xor_sync(0xffffffffu, t, o);
    }
    if (lane == 0) { g_esrc[row * 4 + hh] = s; g_edst[row * 4 + hh] = t; }
}

// ---------------- kernel 3: per (b,h) bitonic sort of valid e_dst -------------
__global__ __launch_bounds__(1024)
void k_sort(const int* __restrict__ mask)
{
    int bh = blockIdx.x;
    int b  = bh >> 2, hh = bh & 3;
    int tid = threadIdx.x;
    __shared__ float key[NN];
    __shared__ int   idx[NN];

    int m = mask[b * NN + tid];
    float e = g_edst[(b * NN + tid) * 4 + hh];
    key[tid] = (m != 0) ? e : FLOATMAX;
    idx[tid] = tid;
    int cnt = __syncthreads_count(m != 0);
    if (tid == 0 && hh == 0) g_nvalid[b] = cnt;

    for (int k = 2; k <= NN; k <<= 1) {
        for (int j = k >> 1; j > 0; j >>= 1) {
            __syncthreads();
            int ixj = tid ^ j;
            if (ixj > tid) {
                bool up = ((tid & k) == 0);
                float ka = key[tid], kb = key[ixj];
                if ((ka > kb) == up) {
                    key[tid] = kb; key[ixj] = ka;
                    int ia = idx[tid]; idx[tid] = idx[ixj]; idx[ixj] = ia;
                }
            }
        }
    }
    __syncthreads();
    g_key [bh * NN + tid] = key[tid];
    g_sidx[bh * NN + tid] = idx[tid];
}

// ---------------- kernel 4: per (b,h) prefix scans + hmean --------------------
__global__ __launch_bounds__(128)
void k_scan()
{
    int bh = blockIdx.x;
    int b = bh >> 2, hh = bh & 3;
    int d = threadIdx.x;
    __shared__ int   sj [NN];
    __shared__ float sw1[NN];
    __shared__ float sw2[NN];
    for (int k = d; k < NN; k += 128) {
        sj[k] = g_sidx[bh * NN + k];
        float e = g_key[bh * NN + k];
        sw1[k] = __expf(0.2f * e);
        sw2[k] = __expf(e);
    }
    __syncthreads();

    const float* hb = g_h + ((size_t)b << 10) * FF + hh * DD + d;

    // mean over all 1024 j (for uniform-softmax rows)
    float m0 = 0.f, m1 = 0.f, m2 = 0.f, m3 = 0.f;
    for (int j = 0; j < NN; j += 8) {
        m0 += hb[(size_t)(j + 0) * FF]; m1 += hb[(size_t)(j + 1) * FF];
        m2 += hb[(size_t)(j + 2) * FF]; m3 += hb[(size_t)(j + 3) * FF];
        m0 += hb[(size_t)(j + 4) * FF]; m1 += hb[(size_t)(j + 5) * FF];
        m2 += hb[(size_t)(j + 6) * FF]; m3 += hb[(size_t)(j + 7) * FF];
    }
    g_hmean[bh * DD + d] = (m0 + m1 + m2 + m3) * (1.f / (float)NN);

    int nv = g_nvalid[b];
    size_t pbase = (size_t)bh * (NN + 1) * DD;
    float* P1 = g_p1 + pbase + d;
    float* P2 = g_p2 + pbase + d;
    P1[0] = 0.f; P2[0] = 0.f;
    if (d == 0) { g_s1[bh * (NN + 1)] = 0.f; g_s2[bh * (NN + 1)] = 0.f; }
    float acc1 = 0.f, acc2 = 0.f, s1 = 0.f, s2 = 0.f;

    // groups past nv write garbage to indices > nv: never read (search bounded by nv)
    for (int k0 = 0; k0 < nv; k0 += 8) {
        float hv[8];
#pragma unroll
        for (int u = 0; u < 8; u++) hv[u] = hb[(size_t)sj[k0 + u] * FF];
#pragma unroll
        for (int u = 0; u < 8; u++) {
            int k = k0 + u;
            acc1 = fmaf(sw1[k], hv[u], acc1);
            acc2 = fmaf(sw2[k], hv[u], acc2);
            P1[(size_t)(k + 1) * DD] = acc1;
            P2[(size_t)(k + 1) * DD] = acc2;
            s1 += sw1[k]; s2 += sw2[k];
            if (d == 0) {
                g_s1[bh * (NN + 1) + k + 1] = s1;
                g_s2[bh * (NN + 1) + k + 1] = s2;
            }
        }
    }
}

// ---------------- kernel 5: per-row combine + residual + LayerNorm ------------
__global__ __launch_bounds__(128)
void k_final(const float* __restrict__ x, const int* __restrict__ mask,
             const float* __restrict__ gamma, const float* __restrict__ beta,
             float* __restrict__ out)
{
    int row  = blockIdx.x;
    int b    = row >> 10;
    int tid  = threadIdx.x;
    int warp = tid >> 5;
    int lane = tid & 31;
    __shared__ float yv[FF];
    __shared__ float red[8];

    int nv = g_nvalid[b];
    bool uni = (mask[row] == 0) || (nv == 0);
    int hh = warp;                           // 4 warps, one head each
    int bh = b * 4 + hh;
    size_t pbase = (size_t)bh * (NN + 1) * DD;

    float4 xr = *reinterpret_cast<const float4*>(&x[(size_t)row * FF + hh * DD + lane * 4]);
    float4 y;
    if (uni) {
        float4 hm = *reinterpret_cast<const float4*>(&g_hmean[bh * DD + lane * 4]);
        y.x = hm.x + xr.x; y.y = hm.y + xr.y; y.z = hm.z + xr.z; y.w = hm.w + xr.w;
    } else {
        float ei = g_esrc[row * 4 + hh];
        float t  = -ei;
        const float* keys = g_key + bh * NN;
        int lo = 0, hi = nv;
        while (lo < hi) {
            int mid = (lo + hi) >> 1;
            if (keys[mid] <= t) lo = mid + 1; else hi = mid;
        }
        int k0 = lo;                         // first index with ej > -ei
        float w1 = __expf(0.2f * ei);
        float w2 = __expf(ei);
        float den = w1 * g_s1[bh * (NN + 1) + k0]
                  + w2 * (g_s2[bh * (NN + 1) + nv] - g_s2[bh * (NN + 1) + k0]);
        float inv = 1.0f / den;
        float4 p1 = *reinterpret_cast<const float4*>(&g_p1[pbase + (size_t)k0 * DD + lane * 4]);
        float4 pa = *reinterpret_cast<const float4*>(&g_p2[pbase + (size_t)k0 * DD + lane * 4]);
        float4 pb = *reinterpret_cast<const float4*>(&g_p2[pbase + (size_t)nv * DD + lane * 4]);
        y.x = (w1 * p1.x + w2 * (pb.x - pa.x)) * inv + xr.x;
        y.y = (w1 * p1.y + w2 * (pb.y - pa.y)) * inv + xr.y;
        y.z = (w1 * p1.z + w2 * (pb.z - pa.z)) * inv + xr.z;
        y.w = (w1 * p1.w + w2 * (pb.w - pa.w)) * inv + xr.w;
    }
    *reinterpret_cast<float4*>(&yv[hh * DD + lane * 4]) = y;
    __syncthreads();

    // LayerNorm over 512 (two-pass, matches jnp.mean/var)
    float s = 0.f;
#pragma unroll
    for (int u = 0; u < 4; u++) s += yv[tid + u * 128];
#pragma unroll
    for (int o = 16; o > 0; o >>= 1) s += __shfl_xor_sync(0xffffffffu, s, o);
    if (lane == 0) red[warp] = s;
    __syncthreads();
    float mu = (red[0] + red[1] + red[2] + red[3]) * (1.0f / (float)FF);

    float q = 0.f;
#pragma unroll
    for (int u = 0; u < 4; u++) {
        float dlt = yv[tid + u * 128] - mu;
        q += dlt * dlt;
    }
#pragma unroll
    for (int o = 16; o > 0; o >>= 1) q += __shfl_xor_sync(0xffffffffu, q, o);
    if (lane == 0) red[4 + warp] = q;
    __syncthreads();
    float var = (red[4] + red[5] + red[6] + red[7]) * (1.0f / (float)FF);
    float rs = rsqrtf(var + LN_EPS);

#pragma unroll
    for (int u = 0; u < 4; u++) {
        int c = tid + u * 128;
        out[(size_t)row * FF + c] = (yv[c] - mu) * rs * gamma[c] + beta[c];
    }
}

// ---------------- launch ------------------------------------------------------
extern "C" void kernel_launch(void* const* d_in, const int* in_sizes, int n_in,
                              void* d_out, int out_size)
{
    const float* x     = (const float*)d_in[0];
    const int*   mask  = (const int*)  d_in[1];
    const float* W     = (const float*)d_in[2];
    const float* a_src = (const float*)d_in[3];
    const float* a_dst = (const float*)d_in[4];
    const float* gamma = (const float*)d_in[5];
    const float* beta  = (const float*)d_in[6];
    float* out = (float*)d_out;

    k_gemm <<<dim3(FF / 128, ROWS / 128), 256>>>(x, W);
    k_eproj<<<(ROWS * HH * 32) / 256, 256>>>(a_src, a_dst);
    k_sort <<<BH, NN>>>(mask);
    k_scan <<<BH, DD>>>();
    k_final<<<ROWS, 128>>>(x, mask, gamma, beta, out);
}

// round 4
// speedup vs baseline: 1.2857x; 1.2857x over previous
#include <cuda_runtime.h>
#include <math.h>

#define BB 8
#define NN 1024
#define FF 512
#define HH 4
#define DD 128
#define ROWS (BB*NN)            // 8192
#define BH   (BB*HH)            // 32
#define TILE 64
#define NT   (NN/TILE)          // 16
#define LN_EPS 1e-5f
#define FLOATMAX 3.402823466e+38f

// ---------------- scratch (static device globals; no allocs allowed) ----------
__device__ float g_h[(size_t)ROWS*FF];                 // 16 MB: h = x @ W
__device__ float g_esrc[ROWS*HH];
__device__ float g_edst[ROWS*HH];
__device__ float g_key [BH*NN];                        // sorted e_dst keys per (b,h)
__device__ int   g_sidx[BH*NN];                        // sorted j indices
__device__ int   g_nvalid[BB];
__device__ float g_p1[(size_t)BH*NN*DD];               // tile-LOCAL inclusive prefixes
__device__ float g_p2[(size_t)BH*NN*DD];
__device__ float g_t1[BH*NT*DD];                       // tile totals
__device__ float g_t2[BH*NT*DD];
__device__ float g_off1[BH*(NT+1)*DD];                 // exclusive tile offsets
__device__ float g_off2[BH*(NT+1)*DD];
__device__ float g_hp[BH*NT*DD];                       // hmean partials
__device__ float g_s1[BH*(NN+1)];                      // scalar prefixes (global after B)
__device__ float g_s2[BH*(NN+1)];
__device__ float g_hmean[BH*DD];

// ---------------- kernel 1: SGEMM  g_h = x @ W  (8192x512x512, fp32) ----------
__global__ __launch_bounds__(256, 2)
void k_gemm(const float* __restrict__ A, const float* __restrict__ Bw)
{
    __shared__ float As[16][132];
    __shared__ float Bs[16][132];
    const int K = FF, Nc = FF;
    int tid = threadIdx.x;
    int rowBase = blockIdx.y * 128;
    int colBase = blockIdx.x * 128;
    int ty = tid >> 4, tx = tid & 15;

    float acc[8][8];
#pragma unroll
    for (int i = 0; i < 8; i++)
#pragma unroll
        for (int j = 0; j < 8; j++) acc[i][j] = 0.f;

    for (int k0 = 0; k0 < K; k0 += 16) {
#pragma unroll
        for (int l = 0; l < 2; l++) {
            int fid = tid + l * 256;
            int r  = fid >> 2;
            int kc = (fid & 3) << 2;
            float4 v = *reinterpret_cast<const float4*>(
                &A[(size_t)(rowBase + r) * K + k0 + kc]);
            As[kc + 0][r] = v.x; As[kc + 1][r] = v.y;
            As[kc + 2][r] = v.z; As[kc + 3][r] = v.w;
        }
#pragma unroll
        for (int l = 0; l < 2; l++) {
            int fid = tid + l * 256;
            int r  = fid >> 5;
            int c4 = (fid & 31) << 2;
            *reinterpret_cast<float4*>(&Bs[r][c4]) =
                *reinterpret_cast<const float4*>(
                    &Bw[(size_t)(k0 + r) * Nc + colBase + c4]);
        }
        __syncthreads();
#pragma unroll
        for (int kk = 0; kk < 16; kk++) {
            float4 a0 = *reinterpret_cast<const float4*>(&As[kk][ty * 8]);
            float4 a1 = *reinterpret_cast<const float4*>(&As[kk][ty * 8 + 4]);
            float4 b0 = *reinterpret_cast<const float4*>(&Bs[kk][tx * 8]);
            float4 b1 = *reinterpret_cast<const float4*>(&Bs[kk][tx * 8 + 4]);
            float ar[8] = {a0.x, a0.y, a0.z, a0.w, a1.x, a1.y, a1.z, a1.w};
            float br[8] = {b0.x, b0.y, b0.z, b0.w, b1.x, b1.y, b1.z, b1.w};
#pragma unroll
            for (int i = 0; i < 8; i++)
#pragma unroll
                for (int j = 0; j < 8; j++)
                    acc[i][j] = fmaf(ar[i], br[j], acc[i][j]);
        }
        __syncthreads();
    }
#pragma unroll
    for (int i = 0; i < 8; i++) {
        int r = rowBase + ty * 8 + i;
        float4 c0 = make_float4(acc[i][0], acc[i][1], acc[i][2], acc[i][3]);
        float4 c1 = make_float4(acc[i][4], acc[i][5], acc[i][6], acc[i][7]);
        *reinterpret_cast<float4*>(&g_h[(size_t)r * Nc + colBase + tx * 8])     = c0;
        *reinterpret_cast<float4*>(&g_h[(size_t)r * Nc + colBase + tx * 8 + 4]) = c1;
    }
}

// ---------------- kernel 2: e_src/e_dst = h . a_src / a_dst  ------------------
__global__ __launch_bounds__(256)
void k_eproj(const float* __restrict__ a_src, const float* __restrict__ a_dst)
{
    int gw   = (blockIdx.x * blockDim.x + threadIdx.x) >> 5;
    int lane = threadIdx.x & 31;
    if (gw >= ROWS * HH) return;
    int row = gw >> 2;
    int hh  = gw & 3;
    float4 hv = *reinterpret_cast<const float4*>(&g_h[(size_t)row * FF + hh * DD + lane * 4]);
    float4 as = *reinterpret_cast<const float4*>(&a_src[hh * DD + lane * 4]);
    float4 ad = *reinterpret_cast<const float4*>(&a_dst[hh * DD + lane * 4]);
    float s = hv.x * as.x + hv.y * as.y + hv.z * as.z + hv.w * as.w;
    float t = hv.x * ad.x + hv.y * ad.y + hv.z * ad.z + hv.w * ad.w;
#pragma unroll
    for (int o = 16; o > 0; o >>= 1) {
        s += __shfl_xor_sync(0xffffffffu, s, o);
        t += __shfl_xor_sync(0xffffffffu, t, o);
    }
    if (lane == 0) { g_esrc[row * 4 + hh] = s; g_edst[row * 4 + hh] = t; }
}

// ---------------- kernel 3: per (b,h) bitonic sort of valid e_dst -------------
__global__ __launch_bounds__(1024)
void k_sort(const int* __restrict__ mask)
{
    int bh = blockIdx.x;
    int b  = bh >> 2, hh = bh & 3;
    int tid = threadIdx.x;
    __shared__ float key[NN];
    __shared__ int   idx[NN];

    int m = mask[b * NN + tid];
    float e = g_edst[(b * NN + tid) * 4 + hh];
    key[tid] = (m != 0) ? e : FLOATMAX;
    idx[tid] = tid;
    int cnt = __syncthreads_count(m != 0);
    if (tid == 0 && hh == 0) g_nvalid[b] = cnt;

    for (int k = 2; k <= NN; k <<= 1) {
        for (int j = k >> 1; j > 0; j >>= 1) {
            __syncthreads();
            int ixj = tid ^ j;
            if (ixj > tid) {
                bool up = ((tid & k) == 0);
                float ka = key[tid], kb = key[ixj];
                if ((ka > kb) == up) {
                    key[tid] = kb; key[ixj] = ka;
                    int ia = idx[tid]; idx[tid] = idx[ixj]; idx[ixj] = ia;
                }
            }
        }
    }
    __syncthreads();
    g_key [bh * NN + tid] = key[tid];
    g_sidx[bh * NN + tid] = idx[tid];
}

// ---------------- kernel 4a: tile-local prefix scans + hmean partials ---------
// grid (NT, BH), block DD. Tile t covers k in [t*64, t*64+64).
// Weights for k >= nvalid are forced to 0 => uniform full-tile loops, and all
// prefixes/totals are globally consistent with zero-padding past nv.
__global__ __launch_bounds__(DD)
void k_scanA()
{
    int t  = blockIdx.x;
    int bh = blockIdx.y;
    int b = bh >> 2, hh = bh & 3;
    int d = threadIdx.x;

    __shared__ int   sj [TILE];
    __shared__ float sw1[TILE];
    __shared__ float sw2[TILE];

    int nv = g_nvalid[b];
    if (d < TILE) {
        int k = t * TILE + d;
        sj[d] = g_sidx[bh * NN + k];
        float e = g_key[bh * NN + k];
        bool v = (k < nv);
        sw1[d] = v ? __expf(0.2f * e) : 0.f;
        sw2[d] = v ? __expf(e) : 0.f;
    }
    __syncthreads();

    const float* hb = g_h + ((size_t)b << 10) * FF + hh * DD + d;
    float* P1 = g_p1 + ((size_t)bh * NN + t * TILE) * DD + d;
    float* P2 = g_p2 + ((size_t)bh * NN + t * TILE) * DD + d;

    float acc1 = 0.f, acc2 = 0.f;
    float hv[8];
#pragma unroll
    for (int u = 0; u < 8; u++) hv[u] = hb[(size_t)sj[u] * FF];
    for (int m0 = 0; m0 < TILE; m0 += 8) {
        float cur[8];
#pragma unroll
        for (int u = 0; u < 8; u++) cur[u] = hv[u];
        if (m0 + 8 < TILE) {
#pragma unroll
            for (int u = 0; u < 8; u++) hv[u] = hb[(size_t)sj[m0 + 8 + u] * FF];
        }
#pragma unroll
        for (int u = 0; u < 8; u++) {
            int m = m0 + u;
            acc1 = fmaf(sw1[m], cur[u], acc1);
            acc2 = fmaf(sw2[m], cur[u], acc2);
            P1[(size_t)m * DD] = acc1;
            P2[(size_t)m * DD] = acc2;
        }
    }
    g_t1[(bh * NT + t) * DD + d] = acc1;
    g_t2[(bh * NT + t) * DD + d] = acc2;

    // scalar tile-local prefixes (one thread; 64 smem reads, overlaps above)
    if (d == 0) {
        float s1 = 0.f, s2 = 0.f;
        int base = bh * (NN + 1) + t * TILE;
#pragma unroll 8
        for (int m = 0; m < TILE; m++) {
            s1 += sw1[m]; s2 += sw2[m];
            g_s1[base + m + 1] = s1;
            g_s2[base + m + 1] = s2;
        }
    }

    // hmean partial over raw j in [t*64, t*64+64)
    float m0a = 0.f, m1a = 0.f, m2a = 0.f, m3a = 0.f;
    const float* hj = g_h + (((size_t)b << 10) + t * TILE) * FF + hh * DD + d;
#pragma unroll 8
    for (int j = 0; j < TILE; j += 4) {
        m0a += hj[(size_t)(j + 0) * FF];
        m1a += hj[(size_t)(j + 1) * FF];
        m2a += hj[(size_t)(j + 2) * FF];
        m3a += hj[(size_t)(j + 3) * FF];
    }
    g_hp[(bh * NT + t) * DD + d] = (m0a + m1a) + (m2a + m3a);
}

// ---------------- kernel 4b: tile offsets + scalar fixup + hmean --------------
__global__ __launch_bounds__(DD)
void k_scanB()
{
    int bh = blockIdx.x;
    int d  = threadIdx.x;

    float o1 = 0.f, o2 = 0.f, hm = 0.f;
#pragma unroll
    for (int t = 0; t < NT; t++) {
        g_off1[(bh * (NT + 1) + t) * DD + d] = o1;
        g_off2[(bh * (NT + 1) + t) * DD + d] = o2;
        o1 += g_t1[(bh * NT + t) * DD + d];
        o2 += g_t2[(bh * NT + t) * DD + d];
        hm += g_hp[(bh * NT + t) * DD + d];
    }
    g_off1[(bh * (NT + 1) + NT) * DD + d] = o1;
    g_off2[(bh * (NT + 1) + NT) * DD + d] = o2;
    g_hmean[bh * DD + d] = hm * (1.f / (float)NN);

    // scalar tile offsets
    __shared__ float so1[NT + 1], so2[NT + 1];
    int base = bh * (NN + 1);
    if (d == 0) {
        float a1 = 0.f, a2 = 0.f;
#pragma unroll
        for (int t = 0; t < NT; t++) {
            so1[t] = a1; so2[t] = a2;
            a1 += g_s1[base + t * TILE + TILE];
            a2 += g_s2[base + t * TILE + TILE];
        }
        so1[NT] = a1; so2[NT] = a2;
        g_s1[base] = 0.f; g_s2[base] = 0.f;
    }
    __syncthreads();
    for (int k = d + 1; k <= NN; k += DD) {
        int t = (k - 1) >> 6;
        g_s1[base + k] += so1[t];
        g_s2[base + k] += so2[t];
    }
}

// ---------------- kernel 5: per-row combine + residual + LayerNorm ------------
__global__ __launch_bounds__(128)
void k_final(const float* __restrict__ x, const int* __restrict__ mask,
             const float* __restrict__ gamma, const float* __restrict__ beta,
             float* __restrict__ out)
{
    int row  = blockIdx.x;
    int b    = row >> 10;
    int tid  = threadIdx.x;
    int warp = tid >> 5;
    int lane = tid & 31;
    __shared__ float yv[FF];
    __shared__ float red[8];

    int nv = g_nvalid[b];
    bool uni = (mask[row] == 0) || (nv == 0);
    int hh = warp;                           // 4 warps, one head each
    int bh = b * 4 + hh;

    float4 xr = *reinterpret_cast<const float4*>(&x[(size_t)row * FF + hh * DD + lane * 4]);
    float4 y;
    if (uni) {
        float4 hm = *reinterpret_cast<const float4*>(&g_hmean[bh * DD + lane * 4]);
        y.x = hm.x + xr.x; y.y = hm.y + xr.y; y.z = hm.z + xr.z; y.w = hm.w + xr.w;
    } else {
        float ei = g_esrc[row * 4 + hh];
        float tt = -ei;
        const float* keys = g_key + bh * NN;
        int lo = 0, hi = nv;
        while (lo < hi) {
            int mid = (lo + hi) >> 1;
            if (keys[mid] <= tt) lo = mid + 1; else hi = mid;
        }
        int k0 = lo;                         // first index with ej > -ei
        int t0 = k0 >> 6, m0 = k0 & 63;
        int tn = nv >> 6, mn = nv & 63;

        float w1 = __expf(0.2f * ei);
        float w2 = __expf(ei);
        float den = w1 * g_s1[bh * (NN + 1) + k0]
                  + w2 * (g_s2[bh * (NN + 1) + nv] - g_s2[bh * (NN + 1) + k0]);
        float inv = 1.0f / den;

        const float4 z4 = make_float4(0.f, 0.f, 0.f, 0.f);
        size_t ob = (size_t)(bh * (NT + 1));
        float4 o1 = *reinterpret_cast<const float4*>(&g_off1[(ob + t0) * DD + lane * 4]);
        float4 o2 = *reinterpret_cast<const float4*>(&g_off2[(ob + t0) * DD + lane * 4]);
        float4 on = *reinterpret_cast<const float4*>(&g_off2[(ob + tn) * DD + lane * 4]);
        float4 l1 = m0 ? *reinterpret_cast<const float4*>(
                        &g_p1[((size_t)bh * NN + k0 - 1) * DD + lane * 4]) : z4;
        float4 l2 = m0 ? *reinterpret_cast<const float4*>(
                        &g_p2[((size_t)bh * NN + k0 - 1) * DD + lane * 4]) : z4;
        float4 ln = mn ? *reinterpret_cast<const float4*>(
                        &g_p2[((size_t)bh * NN + nv - 1) * DD + lane * 4]) : z4;

        float P1x = o1.x + l1.x, P1y = o1.y + l1.y, P1z = o1.z + l1.z, P1w = o1.w + l1.w;
        float Pax = o2.x + l2.x, Pay = o2.y + l2.y, Paz = o2.z + l2.z, Paw = o2.w + l2.w;
        float Pbx = on.x + ln.x, Pby = on.y + ln.y, Pbz = on.z + ln.z, Pbw = on.w + ln.w;

        y.x = (w1 * P1x + w2 * (Pbx - Pax)) * inv + xr.x;
        y.y = (w1 * P1y + w2 * (Pby - Pay)) * inv + xr.y;
        y.z = (w1 * P1z + w2 * (Pbz - Paz)) * inv + xr.z;
        y.w = (w1 * P1w + w2 * (Pbw - Paw)) * inv + xr.w;
    }
    *reinterpret_cast<float4*>(&yv[hh * DD + lane * 4]) = y;
    __syncthreads();

    // LayerNorm over 512 (two-pass, matches jnp.mean/var)
    float s = 0.f;
#pragma unroll
    for (int u = 0; u < 4; u++) s += yv[tid + u * 128];
#pragma unroll
    for (int o = 16; o > 0; o >>= 1) s += __shfl_xor_sync(0xffffffffu, s, o);
    if (lane == 0) red[warp] = s;
    __syncthreads();
    float mu = (red[0] + red[1] + red[2] + red[3]) * (1.0f / (float)FF);

    float q = 0.f;
#pragma unroll
    for (int u = 0; u < 4; u++) {
        float dlt = yv[tid + u * 128] - mu;
        q += dlt * dlt;
    }
#pragma unroll
    for (int o = 16; o > 0; o >>= 1) q += __shfl_xor_sync(0xffffffffu, q, o);
    if (lane == 0) red[4 + warp] = q;
    __syncthreads();
    float var = (red[4] + red[5] + red[6] + red[7]) * (1.0f / (float)FF);
    float rs = rsqrtf(var + LN_EPS);

#pragma unroll
    for (int u = 0; u < 4; u++) {
        int c = tid + u * 128;
        out[(size_t)row * FF + c] = (yv[c] - mu) * rs * gamma[c] + beta[c];
    }
}

// ---------------- launch ------------------------------------------------------
extern "C" void kernel_launch(void* const* d_in, const int* in_sizes, int n_in,
                              void* d_out, int out_size)
{
    const float* x     = (const float*)d_in[0];
    const int*   mask  = (const int*)  d_in[1];
    const float* W     = (const float*)d_in[2];
    const float* a_src = (const float*)d_in[3];
    const float* a_dst = (const float*)d_in[4];
    const float* gamma = (const float*)d_in[5];
    const float* beta  = (const float*)d_in[6];
    float* out = (float*)d_out;

    k_gemm <<<dim3(FF / 128, ROWS / 128), 256>>>(x, W);
    k_eproj<<<(ROWS * HH * 32) / 256, 256>>>(a_src, a_dst);
    k_sort <<<BH, NN>>>(mask);
    k_scanA<<<dim3(NT, BH), DD>>>();
    k_scanB<<<BH, DD>>>();
    k_final<<<ROWS, 128>>>(x, mask, gamma, beta, out);
}

// round 8
// speedup vs baseline: 1.8514x; 1.4400x over previous
#include <cuda_runtime.h>
#include <cuda_bf16.h>
#include <stdint.h>
#include <cstdint>
#include <math.h>

#define BB 8
#define NN 1024
#define FF 512
#define HH 4
#define DD 128
#define ROWS (BB*NN)            // 8192
#define BH   (BB*HH)            // 32
#define TILE 64
#define NT   (NN/TILE)          // 16
#define LN_EPS 1e-5f
#define FLOATMAX 3.402823466e+38f

// ---------------- scratch (static device globals; no allocs allowed) ----------
__device__ float g_h[(size_t)ROWS*FF];                 // 16 MB: h = x @ W
__device__ __align__(16) __nv_bfloat16 g_ahi[(size_t)ROWS*FF];
__device__ __align__(16) __nv_bfloat16 g_alo[(size_t)ROWS*FF];
__device__ __align__(16) __nv_bfloat16 g_bhi[FF*FF];   // W^T, [N=512][K=512]
__device__ __align__(16) __nv_bfloat16 g_blo[FF*FF];
__device__ float g_esrc[ROWS*HH];
__device__ float g_edst[ROWS*HH];
__device__ float g_key [BH*NN];
__device__ int   g_sidx[BH*NN];
__device__ int   g_nvalid[BB];
__device__ float g_p1[(size_t)BH*NN*DD];               // tile-LOCAL inclusive prefixes
__device__ float g_p2[(size_t)BH*NN*DD];
__device__ float g_t1[BH*NT*DD];
__device__ float g_t2[BH*NT*DD];
__device__ float g_off1[BH*(NT+1)*DD];
__device__ float g_off2[BH*(NT+1)*DD];
__device__ float g_hp[BH*NT*DD];
__device__ float g_s1[BH*(NN+1)];
__device__ float g_s2[BH*(NN+1)];
__device__ float g_hmean[BH*DD];

// ---------------- helpers -------------------------------------------------------
__device__ __forceinline__ uint32_t smem_u32(const void* p) {
    uint32_t a;
    asm("{ .reg .u64 t; cvta.to.shared.u64 t, %1; cvt.u32.u64 %0, t; }"
        : "=r"(a) : "l"(p));
    return a;
}
__device__ __forceinline__ void cp16(uint32_t dst, const void* src) {
    asm volatile("cp.async.cg.shared.global [%0], [%1], 16;"
                 :: "r"(dst), "l"(src) : "memory");
}
__device__ __forceinline__ void ldmx4(uint32_t* r, uint32_t addr) {
    asm volatile("ldmatrix.sync.aligned.m8n8.x4.shared.b16 {%0,%1,%2,%3}, [%4];"
                 : "=r"(r[0]), "=r"(r[1]), "=r"(r[2]), "=r"(r[3]) : "r"(addr));
}
__device__ __forceinline__ void ldmx2(uint32_t* r, uint32_t addr) {
    asm volatile("ldmatrix.sync.aligned.m8n8.x2.shared.b16 {%0,%1}, [%2];"
                 : "=r"(r[0]), "=r"(r[1]) : "r"(addr));
}
__device__ __forceinline__ void mma16816(float* c, const uint32_t* a, const uint32_t* b) {
    asm volatile(
        "mma.sync.aligned.m16n8k16.row.col.f32.bf16.bf16.f32 "
        "{%0,%1,%2,%3}, {%4,%5,%6,%7}, {%8,%9}, {%0,%1,%2,%3};"
        : "+f"(c[0]), "+f"(c[1]), "+f"(c[2]), "+f"(c[3])
        : "r"(a[0]), "r"(a[1]), "r"(a[2]), "r"(a[3]), "r"(b[0]), "r"(b[1]));
}

// ---------------- kernel 0a: split x -> bf16 hi/lo -----------------------------
__global__ __launch_bounds__(256)
void k_convA(const float* __restrict__ x)
{
    size_t i = ((size_t)blockIdx.x * 256 + threadIdx.x) * 8;
    float4 a = *reinterpret_cast<const float4*>(x + i);
    float4 b = *reinterpret_cast<const float4*>(x + i + 4);
    float v[8] = {a.x, a.y, a.z, a.w, b.x, b.y, b.z, b.w};
    union { __nv_bfloat16 h[8]; uint4 u; } hi, lo;
#pragma unroll
    for (int u = 0; u < 8; u++) {
        __nv_bfloat16 hv = __float2bfloat16(v[u]);
        hi.h[u] = hv;
        lo.h[u] = __float2bfloat16(v[u] - __bfloat162float(hv));
    }
    *reinterpret_cast<uint4*>(g_ahi + i) = hi.u;
    *reinterpret_cast<uint4*>(g_alo + i) = lo.u;
}

// ---------------- kernel 0b: split+transpose W -> [N][K] bf16 hi/lo ------------
__global__ __launch_bounds__(256)
void k_convB(const float* __restrict__ W)
{
    __shared__ float s[32][33];
    int tx = threadIdx.x, ty = threadIdx.y;
    int kt = blockIdx.x * 32, nt = blockIdx.y * 32;
#pragma unroll
    for (int i = 0; i < 4; i++)
        s[ty + i * 8][tx] = W[(size_t)(kt + ty + i * 8) * FF + nt + tx];
    __syncthreads();
#pragma unroll
    for (int i = 0; i < 4; i++) {
        int n = nt + ty + i * 8;
        int k = kt + tx;
        float v = s[tx][ty + i * 8];
        __nv_bfloat16 hv = __float2bfloat16(v);
        g_bhi[(size_t)n * FF + k] = hv;
        g_blo[(size_t)n * FF + k] = __float2bfloat16(v - __bfloat162float(hv));
    }
}

// ---------------- kernel 1: mma.sync bf16x3 GEMM  g_h = x @ W ------------------
// CTA tile 128x128, warp tile 64x32 (warps 2x4), K stages of 32, cp.async x2 buf.
#define KCH   32
#define NSTG  (FF/KCH)          // 16
#define PADE  40                // smem row stride in bf16 elems (80 B)
#define AB    (128*PADE*2)      // bytes per array per buffer (10240)
#define STG   (4*AB)            // bytes per stage buffer (40960)

__device__ __forceinline__ void gemm_issue(int s, int rowBase, int colBase,
                                           uint32_t sb, int tid)
{
    uint32_t dbase = sb + (uint32_t)((s & 1) * STG);
#pragma unroll
    for (int l = 0; l < 2; l++) {
        int idx = tid + l * 256;          // 0..511
        int row = idx >> 2, q = idx & 3;
        uint32_t d = dbase + (uint32_t)(row * 80 + q * 16);
        size_t ga = (size_t)(rowBase + row) * FF + s * KCH + q * 8;
        size_t gb = (size_t)(colBase + row) * FF + s * KCH + q * 8;
        cp16(d + 0 * AB, g_ahi + ga);
        cp16(d + 1 * AB, g_alo + ga);
        cp16(d + 2 * AB, g_bhi + gb);
        cp16(d + 3 * AB, g_blo + gb);
    }
    asm volatile("cp.async.commit_group;" ::: "memory");
}

__global__ __launch_bounds__(256, 1)
void k_gemm_mma()
{
    extern __shared__ __align__(16) char smc[];
    const uint32_t sb = smem_u32(smc);
    const int tid = threadIdx.x, wid = tid >> 5, lane = tid & 31;
    const int wm = wid & 1, wn = wid >> 1;
    const int rowBase = blockIdx.y * 128, colBase = blockIdx.x * 128;

    float acc[4][4][4];
#pragma unroll
    for (int i = 0; i < 4; i++)
#pragma unroll
        for (int j = 0; j < 4; j++)
#pragma unroll
            for (int c = 0; c < 4; c++) acc[i][j][c] = 0.f;

    gemm_issue(0, rowBase, colBase, sb, tid);

    for (int s = 0; s < NSTG; s++) {
        if (s + 1 < NSTG) {
            gemm_issue(s + 1, rowBase, colBase, sb, tid);
            asm volatile("cp.async.wait_group 1;" ::: "memory");
        } else {
            asm volatile("cp.async.wait_group 0;" ::: "memory");
        }
        __syncthreads();

        uint32_t base = sb + (uint32_t)((s & 1) * STG);
#pragma unroll
        for (int ks = 0; ks < 2; ks++) {
            const int kb = ks * 32;       // byte offset of k16 step (16 elems)
            uint32_t ah[4][4], al[4][4], bh[4][2], bl[4][2];
#pragma unroll
            for (int i = 0; i < 4; i++) {
                int row = wm * 64 + i * 16 + (lane & 15);
                uint32_t ad = base + (uint32_t)(row * 80 + kb + (lane >> 4) * 16);
                ldmx4(ah[i], ad);
                ldmx4(al[i], ad + AB);
            }
#pragma unroll
            for (int j = 0; j < 4; j++) {
                int nrow = wn * 32 + j * 8 + (lane & 7);
                uint32_t bd = base + (uint32_t)(2 * AB + nrow * 80 + kb + ((lane >> 3) & 1) * 16);
                ldmx2(bh[j], bd);
                ldmx2(bl[j], bd + AB);
            }
#pragma unroll
            for (int i = 0; i < 4; i++)
#pragma unroll
                for (int j = 0; j < 4; j++) {
                    mma16816(acc[i][j], ah[i], bh[j]);
                    mma16816(acc[i][j], ah[i], bl[j]);
                    mma16816(acc[i][j], al[i], bh[j]);
                }
        }
        __syncthreads();
    }

    // epilogue: fragment -> gmem (float2 per fragment row)
    const int r0 = rowBase + wm * 64, c0 = colBase + wn * 32;
#pragma unroll
    for (int i = 0; i < 4; i++)
#pragma unroll
        for (int j = 0; j < 4; j++) {
            int rr = r0 + i * 16 + (lane >> 2);
            int cc = c0 + j * 8 + (lane & 3) * 2;
            float2 v0 = make_float2(acc[i][j][0], acc[i][j][1]);
            float2 v1 = make_float2(acc[i][j][2], acc[i][j][3]);
            *reinterpret_cast<float2*>(&g_h[(size_t)rr * FF + cc]) = v0;
            *reinterpret_cast<float2*>(&g_h[(size_t)(rr + 8) * FF + cc]) = v1;
        }
}

// ---------------- kernel 2: e_src/e_dst = h . a_src / a_dst  ------------------
__global__ __launch_bounds__(256)
void k_eproj(const float* __restrict__ a_src, const float* __restrict__ a_dst)
{
    int gw   = (blockIdx.x * blockDim.x + threadIdx.x) >> 5;
    int lane = threadIdx.x & 31;
    if (gw >= ROWS * HH) return;
    int row = gw >> 2;
    int hh  = gw & 3;
    float4 hv = *reinterpret_cast<const float4*>(&g_h[(size_t)row * FF + hh * DD + lane * 4]);
    float4 as = *reinterpret_cast<const float4*>(&a_src[hh * DD + lane * 4]);
    float4 ad = *reinterpret_cast<const float4*>(&a_dst[hh * DD + lane * 4]);
    float s = hv.x * as.x + hv.y * as.y + hv.z * as.z + hv.w * as.w;
    float t = hv.x * ad.x + hv.y * ad.y + hv.z * ad.z + hv.w * ad.w;
#pragma unroll
    for (int o = 16; o > 0; o >>= 1) {
        s += __shfl_xor_sync(0xffffffffu, s, o);
        t += __shfl_xor_sync(0xffffffffu, t, o);
    }
    if (lane == 0) { g_esrc[row * 4 + hh] = s; g_edst[row * 4 + hh] = t; }
}

// ---------------- kernel 3: per (b,h) bitonic sort of valid e_dst -------------
__global__ __launch_bounds__(1024)
void k_sort(const int* __restrict__ mask)
{
    int bh = blockIdx.x;
    int b  = bh >> 2, hh = bh & 3;
    int tid = threadIdx.x;
    __shared__ float key[NN];
    __shared__ int   idx[NN];

    int m = mask[b * NN + tid];
    float e = g_edst[(b * NN + tid) * 4 + hh];
    key[tid] = (m != 0) ? e : FLOATMAX;
    idx[tid] = tid;
    int cnt = __syncthreads_count(m != 0);
    if (tid == 0 && hh == 0) g_nvalid[b] = cnt;

    for (int k = 2; k <= NN; k <<= 1) {
        for (int j = k >> 1; j > 0; j >>= 1) {
            __syncthreads();
            int ixj = tid ^ j;
            if (ixj > tid) {
                bool up = ((tid & k) == 0);
                float ka = key[tid], kb = key[ixj];
                if ((ka > kb) == up) {
                    key[tid] = kb; key[ixj] = ka;
                    int ia = idx[tid]; idx[tid] = idx[ixj]; idx[ixj] = ia;
                }
            }
        }
    }
    __syncthreads();
    g_key [bh * NN + tid] = key[tid];
    g_sidx[bh * NN + tid] = idx[tid];
}

// ---------------- kernel 4a: tile-local prefix scans + hmean partials ---------
__global__ __launch_bounds__(DD)
void k_scanA()
{
    int t  = blockIdx.x;
    int bh = blockIdx.y;
    int b = bh >> 2, hh = bh & 3;
    int d = threadIdx.x;

    __shared__ int   sj [TILE];
    __shared__ float sw1[TILE];
    __shared__ float sw2[TILE];

    int nv = g_nvalid[b];
    if (d < TILE) {
        int k = t * TILE + d;
        sj[d] = g_sidx[bh * NN + k];
        float e = g_key[bh * NN + k];
        bool v = (k < nv);
        sw1[d] = v ? __expf(0.2f * e) : 0.f;
        sw2[d] = v ? __expf(e) : 0.f;
    }
    __syncthreads();

    const float* hb = g_h + ((size_t)b << 10) * FF + hh * DD + d;
    float* P1 = g_p1 + ((size_t)bh * NN + t * TILE) * DD + d;
    float* P2 = g_p2 + ((size_t)bh * NN + t * TILE) * DD + d;

    float acc1 = 0.f, acc2 = 0.f;
    float hv[8];
#pragma unroll
    for (int u = 0; u < 8; u++) hv[u] = hb[(size_t)sj[u] * FF];
    for (int m0 = 0; m0 < TILE; m0 += 8) {
        float cur[8];
#pragma unroll
        for (int u = 0; u < 8; u++) cur[u] = hv[u];
        if (m0 + 8 < TILE) {
#pragma unroll
            for (int u = 0; u < 8; u++) hv[u] = hb[(size_t)sj[m0 + 8 + u] * FF];
        }
#pragma unroll
        for (int u = 0; u < 8; u++) {
            int m = m0 + u;
            acc1 = fmaf(sw1[m], cur[u], acc1);
            acc2 = fmaf(sw2[m], cur[u], acc2);
            P1[(size_t)m * DD] = acc1;
            P2[(size_t)m * DD] = acc2;
        }
    }
    g_t1[(bh * NT + t) * DD + d] = acc1;
    g_t2[(bh * NT + t) * DD + d] = acc2;

    if (d == 0) {
        float s1 = 0.f, s2 = 0.f;
        int base = bh * (NN + 1) + t * TILE;
#pragma unroll 8
        for (int m = 0; m < TILE; m++) {
            s1 += sw1[m]; s2 += sw2[m];
            g_s1[base + m + 1] = s1;
            g_s2[base + m + 1] = s2;
        }
    }

    float m0a = 0.f, m1a = 0.f, m2a = 0.f, m3a = 0.f;
    const float* hj = g_h + (((size_t)b << 10) + t * TILE) * FF + hh * DD + d;
#pragma unroll 8
    for (int j = 0; j < TILE; j += 4) {
        m0a += hj[(size_t)(j + 0) * FF];
        m1a += hj[(size_t)(j + 1) * FF];
        m2a += hj[(size_t)(j + 2) * FF];
        m3a += hj[(size_t)(j + 3) * FF];
    }
    g_hp[(bh * NT + t) * DD + d] = (m0a + m1a) + (m2a + m3a);
}

// ---------------- kernel 4b: tile offsets + scalar fixup + hmean --------------
__global__ __launch_bounds__(DD)
void k_scanB()
{
    int bh = blockIdx.x;
    int d  = threadIdx.x;

    float o1 = 0.f, o2 = 0.f, hm = 0.f;
#pragma unroll
    for (int t = 0; t < NT; t++) {
        g_off1[(bh * (NT + 1) + t) * DD + d] = o1;
        g_off2[(bh * (NT + 1) + t) * DD + d] = o2;
        o1 += g_t1[(bh * NT + t) * DD + d];
        o2 += g_t2[(bh * NT + t) * DD + d];
        hm += g_hp[(bh * NT + t) * DD + d];
    }
    g_off1[(bh * (NT + 1) + NT) * DD + d] = o1;
    g_off2[(bh * (NT + 1) + NT) * DD + d] = o2;
    g_hmean[bh * DD + d] = hm * (1.f / (float)NN);

    __shared__ float so1[NT + 1], so2[NT + 1];
    int base = bh * (NN + 1);
    if (d == 0) {
        float a1 = 0.f, a2 = 0.f;
#pragma unroll
        for (int t = 0; t < NT; t++) {
            so1[t] = a1; so2[t] = a2;
            a1 += g_s1[base + t * TILE + TILE];
            a2 += g_s2[base + t * TILE + TILE];
        }
        so1[NT] = a1; so2[NT] = a2;
        g_s1[base] = 0.f; g_s2[base] = 0.f;
    }
    __syncthreads();
    for (int k = d + 1; k <= NN; k += DD) {
        int t = (k - 1) >> 6;
        g_s1[base + k] += so1[t];
        g_s2[base + k] += so2[t];
    }
}

// ---------------- kernel 5: per-row combine + residual + LayerNorm ------------
__global__ __launch_bounds__(128)
void k_final(const float* __restrict__ x, const int* __restrict__ mask,
             const float* __restrict__ gamma, const float* __restrict__ beta,
             float* __restrict__ out)
{
    int row  = blockIdx.x;
    int b    = row >> 10;
    int tid  = threadIdx.x;
    int warp = tid >> 5;
    int lane = tid & 31;
    __shared__ float yv[FF];
    __shared__ float red[8];

    int nv = g_nvalid[b];
    bool uni = (mask[row] == 0) || (nv == 0);
    int hh = warp;
    int bh = b * 4 + hh;

    float4 xr = *reinterpret_cast<const float4*>(&x[(size_t)row * FF + hh * DD + lane * 4]);
    float4 y;
    if (uni) {
        float4 hm = *reinterpret_cast<const float4*>(&g_hmean[bh * DD + lane * 4]);
        y.x = hm.x + xr.x; y.y = hm.y + xr.y; y.z = hm.z + xr.z; y.w = hm.w + xr.w;
    } else {
        float ei = g_esrc[row * 4 + hh];
        float tt = -ei;
        const float* keys = g_key + bh * NN;
        int lo = 0, hi = nv;
        while (lo < hi) {
            int mid = (lo + hi) >> 1;
            if (keys[mid] <= tt) lo = mid + 1; else hi = mid;
        }
        int k0 = lo;
        int t0 = k0 >> 6, m0 = k0 & 63;
        int tn = nv >> 6, mn = nv & 63;

        float w1 = __expf(0.2f * ei);
        float w2 = __expf(ei);
        float den = w1 * g_s1[bh * (NN + 1) + k0]
                  + w2 * (g_s2[bh * (NN + 1) + nv] - g_s2[bh * (NN + 1) + k0]);
        float inv = 1.0f / den;

        const float4 z4 = make_float4(0.f, 0.f, 0.f, 0.f);
        size_t ob = (size_t)(bh * (NT + 1));
        float4 o1 = *reinterpret_cast<const float4*>(&g_off1[(ob + t0) * DD + lane * 4]);
        float4 o2 = *reinterpret_cast<const float4*>(&g_off2[(ob + t0) * DD + lane * 4]);
        float4 on = *reinterpret_cast<const float4*>(&g_off2[(ob + tn) * DD + lane * 4]);
        float4 l1 = m0 ? *reinterpret_cast<const float4*>(
                        &g_p1[((size_t)bh * NN + k0 - 1) * DD + lane * 4]) : z4;
        float4 l2 = m0 ? *reinterpret_cast<const float4*>(
                        &g_p2[((size_t)bh * NN + k0 - 1) * DD + lane * 4]) : z4;
        float4 ln = mn ? *reinterpret_cast<const float4*>(
                        &g_p2[((size_t)bh * NN + nv - 1) * DD + lane * 4]) : z4;

        float P1x = o1.x + l1.x, P1y = o1.y + l1.y, P1z = o1.z + l1.z, P1w = o1.w + l1.w;
        float Pax = o2.x + l2.x, Pay = o2.y + l2.y, Paz = o2.z + l2.z, Paw = o2.w + l2.w;
        float Pbx = on.x + ln.x, Pby = on.y + ln.y, Pbz = on.z + ln.z, Pbw = on.w + ln.w;

        y.x = (w1 * P1x + w2 * (Pbx - Pax)) * inv + xr.x;
        y.y = (w1 * P1y + w2 * (Pby - Pay)) * inv + xr.y;
        y.z = (w1 * P1z + w2 * (Pbz - Paz)) * inv + xr.z;
        y.w = (w1 * P1w + w2 * (Pbw - Paw)) * inv + xr.w;
    }
    *reinterpret_cast<float4*>(&yv[hh * DD + lane * 4]) = y;
    __syncthreads();

    float s = 0.f;
#pragma unroll
    for (int u = 0; u < 4; u++) s += yv[tid + u * 128];
#pragma unroll
    for (int o = 16; o > 0; o >>= 1) s += __shfl_xor_sync(0xffffffffu, s, o);
    if (lane == 0) red[warp] = s;
    __syncthreads();
    float mu = (red[0] + red[1] + red[2] + red[3]) * (1.0f / (float)FF);

    float q = 0.f;
#pragma unroll
    for (int u = 0; u < 4; u++) {
        float dlt = yv[tid + u * 128] - mu;
        q += dlt * dlt;
    }
#pragma unroll
    for (int o = 16; o > 0; o >>= 1) q += __shfl_xor_sync(0xffffffffu, q, o);
    if (lane == 0) red[4 + warp] = q;
    __syncthreads();
    float var = (red[4] + red[5] + red[6] + red[7]) * (1.0f / (float)FF);
    float rs = rsqrtf(var + LN_EPS);

#pragma unroll
    for (int u = 0; u < 4; u++) {
        int c = tid + u * 128;
        out[(size_t)row * FF + c] = (yv[c] - mu) * rs * gamma[c] + beta[c];
    }
}

// ---------------- launch ------------------------------------------------------
extern "C" void kernel_launch(void* const* d_in, const int* in_sizes, int n_in,
                              void* d_out, int out_size)
{
    const float* x     = (const float*)d_in[0];
    const int*   mask  = (const int*)  d_in[1];
    const float* W     = (const float*)d_in[2];
    const float* a_src = (const float*)d_in[3];
    const float* a_dst = (const float*)d_in[4];
    const float* gamma = (const float*)d_in[5];
    const float* beta  = (const float*)d_in[6];
    float* out = (float*)d_out;

    static int smem_set = 0;
    if (!smem_set) {
        cudaFuncSetAttribute(k_gemm_mma,
                             cudaFuncAttributeMaxDynamicSharedMemorySize, 2 * STG);
        smem_set = 1;
    }

    k_convA<<<(ROWS * FF) / (256 * 8), 256>>>(x);
    k_convB<<<dim3(FF / 32, FF / 32), dim3(32, 8)>>>(W);
    k_gemm_mma<<<dim3(FF / 128, ROWS / 128), 256, 2 * STG>>>();
    k_eproj<<<(ROWS * HH * 32) / 256, 256>>>(a_src, a_dst);
    k_sort <<<BH, NN>>>(mask);
    k_scanA<<<dim3(NT, BH), DD>>>();
    k_scanB<<<BH, DD>>>();
    k_final<<<ROWS, 128>>>(x, mask, gamma, beta, out);
}

// round 13
// speedup vs baseline: 2.1537x; 1.1633x over previous
#include <cuda_runtime.h>
#include <cuda_bf16.h>
#include <stdint.h>
#include <cstdint>
#include <math.h>

#define BB 8
#define NN 1024
#define FF 512
#define HH 4
#define DD 128
#define ROWS (BB*NN)            // 8192
#define BH   (BB*HH)            // 32
#define TILE 64
#define NT   (NN/TILE)          // 16
#define LN_EPS 1e-5f
#define FLOATMAX 3.402823466e+38f

// GEMM staging: K chunks of 64 elems (128 B/row), tile = 128 rows x 128 B = 16 KB
#define KC    64
#define NSTG  (FF/KC)           // 8
#define TILEB 16384
#define STGB  (4*TILEB)         // 64 KB per stage (Ahi,Alo,Bhi,Blo)
#define NBUF  3
#define SMEM_GEMM (1024 + NBUF*STGB)   // 197632

// ---------------- scratch (static device globals; no allocs allowed) ----------
__device__ float g_h[(size_t)ROWS*FF];                 // 16 MB: h = x @ W
// tiled+swizzled bf16 operands: tile (rb*8+kc) is 16KB contiguous,
// inside: byte(r, c16) at r*128 + ((c16 ^ (r&7))*16)
__device__ __align__(128) __nv_bfloat16 g_ahi[(size_t)ROWS*FF];
__device__ __align__(128) __nv_bfloat16 g_alo[(size_t)ROWS*FF];
__device__ __align__(128) __nv_bfloat16 g_bhi[FF*FF];
__device__ __align__(128) __nv_bfloat16 g_blo[FF*FF];
__device__ float g_esrc[ROWS*HH];
__device__ float g_edst[ROWS*HH];
__device__ float g_key [BH*NN];
__device__ int   g_sidx[BH*NN];
__device__ int   g_nvalid[BB];
__device__ float g_p1[(size_t)BH*NN*DD];               // tile-LOCAL inclusive prefixes
__device__ float g_p2[(size_t)BH*NN*DD];
__device__ float g_t1[BH*NT*DD];
__device__ float g_t2[BH*NT*DD];
__device__ float g_off1[BH*(NT+1)*DD];
__device__ float g_off2[BH*(NT+1)*DD];
__device__ float g_hp[BH*NT*DD];
__device__ float g_s1[BH*(NN+1)];
__device__ float g_s2[BH*(NN+1)];
__device__ float g_hmean[BH*DD];

// ---------------- helpers -------------------------------------------------------
__device__ __forceinline__ uint32_t smem_u32(const void* p) {
    uint32_t a;
    asm("{ .reg .u64 t; cvta.to.shared.u64 t, %1; cvt.u32.u64 %0, t; }"
        : "=r"(a) : "l"(p));
    return a;
}
__device__ __forceinline__ void ldmx4(uint32_t* r, uint32_t addr) {
    asm volatile("ldmatrix.sync.aligned.m8n8.x4.shared.b16 {%0,%1,%2,%3}, [%4];"
                 : "=r"(r[0]), "=r"(r[1]), "=r"(r[2]), "=r"(r[3]) : "r"(addr));
}
__device__ __forceinline__ void ldmx2(uint32_t* r, uint32_t addr) {
    asm volatile("ldmatrix.sync.aligned.m8n8.x2.shared.b16 {%0,%1}, [%2];"
                 : "=r"(r[0]), "=r"(r[1]) : "r"(addr));
}
__device__ __forceinline__ void mma16816(float* c, const uint32_t* a, const uint32_t* b) {
    asm volatile(
        "mma.sync.aligned.m16n8k16.row.col.f32.bf16.bf16.f32 "
        "{%0,%1,%2,%3}, {%4,%5,%6,%7}, {%8,%9}, {%0,%1,%2,%3};"
        : "+f"(c[0]), "+f"(c[1]), "+f"(c[2]), "+f"(c[3])
        : "r"(a[0]), "r"(a[1]), "r"(a[2]), "r"(a[3]), "r"(b[0]), "r"(b[1]));
}
__device__ __forceinline__ void mbar_wait(uint32_t mbar, uint32_t parity) {
    asm volatile(
        "{\n\t.reg .pred P;\n"
        "W1_%=:\n\t"
        "mbarrier.try_wait.parity.acquire.cta.shared::cta.b64 P, [%0], %1, 0x989680;\n\t"
        "@P bra.uni W2_%=;\n\t"
        "bra.uni W1_%=;\n"
        "W2_%=:\n\t}"
        :: "r"(mbar), "r"(parity) : "memory");
}
__device__ __forceinline__ void bulk_g2s(uint32_t dst, const void* src,
                                         uint32_t bytes, uint32_t mbar) {
    asm volatile(
        "cp.async.bulk.shared::cluster.global.mbarrier::complete_tx::bytes "
        "[%0], [%1], %2, [%3];"
        :: "r"(dst), "l"(src), "r"(bytes), "r"(mbar) : "memory");
}

// ---------------- kernel 0a: split x -> tiled/swizzled bf16 hi/lo --------------
__global__ __launch_bounds__(256)
void k_convA(const float* __restrict__ x)
{
    size_t i = ((size_t)blockIdx.x * 256 + threadIdx.x) * 8;
    int row = (int)(i >> 9);
    int k   = (int)(i & 511);
    int rb = row >> 7, r = row & 127;
    int kc = k >> 6,  c = (k & 63) >> 3;
    size_t off = ((size_t)(rb * 8 + kc) << 14) + (size_t)r * 128
               + (size_t)((c ^ (r & 7)) << 4);

    float4 a = *reinterpret_cast<const float4*>(x + i);
    float4 b = *reinterpret_cast<const float4*>(x + i + 4);
    float v[8] = {a.x, a.y, a.z, a.w, b.x, b.y, b.z, b.w};
    union { __nv_bfloat16 h[8]; uint4 u; } hi, lo;
#pragma unroll
    for (int u = 0; u < 8; u++) {
        __nv_bfloat16 hv = __float2bfloat16(v[u]);
        hi.h[u] = hv;
        lo.h[u] = __float2bfloat16(v[u] - __bfloat162float(hv));
    }
    *reinterpret_cast<uint4*>(reinterpret_cast<char*>(g_ahi) + off) = hi.u;
    *reinterpret_cast<uint4*>(reinterpret_cast<char*>(g_alo) + off) = lo.u;
}

// ---------------- kernel 0b: split+transpose W -> tiled/swizzled [N][K] --------
__global__ __launch_bounds__(256)
void k_convB(const float* __restrict__ W)
{
    __shared__ float ts[64][65];
    int tid = threadIdx.x;
    int kt = blockIdx.x * 64, nt = blockIdx.y * 64;
#pragma unroll
    for (int p = 0; p < 16; p++) {
        int idx = tid + p * 256;
        int kl = idx >> 6, nl = idx & 63;
        ts[nl][kl] = W[(size_t)(kt + kl) * FF + nt + nl];
    }
    __syncthreads();
#pragma unroll
    for (int v = 0; v < 2; v++) {
        int u  = tid & 7;
        int nl = (tid >> 3) + v * 32;
        union { __nv_bfloat16 h[8]; uint4 q; } hi, lo;
#pragma unroll
        for (int w = 0; w < 8; w++) {
            float val = ts[nl][u * 8 + w];
            __nv_bfloat16 hv = __float2bfloat16(val);
            hi.h[w] = hv;
            lo.h[w] = __float2bfloat16(val - __bfloat162float(hv));
        }
        int n = nt + nl;
        int cb = n >> 7, r = n & 127, kc = kt >> 6;
        size_t off = ((size_t)(cb * 8 + kc) << 14) + (size_t)r * 128
                   + (size_t)((u ^ (r & 7)) << 4);
        *reinterpret_cast<uint4*>(reinterpret_cast<char*>(g_bhi) + off) = hi.q;
        *reinterpret_cast<uint4*>(reinterpret_cast<char*>(g_blo) + off) = lo.q;
    }
}

// ---------------- kernel 1: bulk-TMA + mma.sync bf16x3 GEMM + fused eproj ------
// grid (4, 64): CTA = 128 rows x 128 cols (= one head). 256 thr, warps 2x4.
__global__ __launch_bounds__(256, 1)
void k_gemm_mma(const float* __restrict__ a_src, const float* __restrict__ a_dst)
{
    extern __shared__ __align__(128) char smc[];
    const uint32_t sb = smem_u32(smc);
    const int tid = threadIdx.x, wid = tid >> 5, lane = tid & 31;
    const int wm = wid & 1, wn = wid >> 1;
    const int rowBlock = blockIdx.y, head = blockIdx.x;
    const int rowBase = rowBlock * 128;

    const uint32_t mb  = sb;
    const uint32_t stg = sb + 1024;

    if (tid == 0) {
#pragma unroll
        for (int i = 0; i < NBUF; i++)
            asm volatile("mbarrier.init.shared.b64 [%0], %1;"
                         :: "r"(mb + 8u * i), "r"(1u) : "memory");
    }
    __syncthreads();

    const char* gA0 = reinterpret_cast<const char*>(g_ahi) + (size_t)rowBlock * 8 * TILEB;
    const char* gA1 = reinterpret_cast<const char*>(g_alo) + (size_t)rowBlock * 8 * TILEB;
    const char* gB0 = reinterpret_cast<const char*>(g_bhi) + (size_t)head * 8 * TILEB;
    const char* gB1 = reinterpret_cast<const char*>(g_blo) + (size_t)head * 8 * TILEB;

    auto issue = [&](int s) {
        int buf = s % NBUF;
        uint32_t mbar = mb + 8u * buf;
        uint32_t d = stg + (uint32_t)buf * STGB;
        asm volatile("mbarrier.arrive.expect_tx.shared.b64 _, [%0], %1;"
                     :: "r"(mbar), "r"((uint32_t)STGB) : "memory");
        bulk_g2s(d + 0 * TILEB, gA0 + (size_t)s * TILEB, TILEB, mbar);
        bulk_g2s(d + 1 * TILEB, gA1 + (size_t)s * TILEB, TILEB, mbar);
        bulk_g2s(d + 2 * TILEB, gB0 + (size_t)s * TILEB, TILEB, mbar);
        bulk_g2s(d + 3 * TILEB, gB1 + (size_t)s * TILEB, TILEB, mbar);
    };
    if (tid == 0) { issue(0); issue(1); issue(2); }

    float acc[4][4][4];
#pragma unroll
    for (int i = 0; i < 4; i++)
#pragma unroll
        for (int j = 0; j < 4; j++)
#pragma unroll
            for (int c = 0; c < 4; c++) acc[i][j][c] = 0.f;

    for (int s = 0; s < NSTG; s++) {
        int buf = s % NBUF;
        mbar_wait(mb + 8u * buf, (uint32_t)((s / NBUF) & 1));
        uint32_t base = stg + (uint32_t)buf * STGB;
#pragma unroll
        for (int ks = 0; ks < 4; ks++) {
            uint32_t ah[4][4], al[4][4], bh[4][2], bl[4][2];
#pragma unroll
            for (int i = 0; i < 4; i++) {
                int r = wm * 64 + i * 16 + (lane & 15);
                int c = ks * 2 + (lane >> 4);
                uint32_t ad = base + (uint32_t)(r * 128 + ((c ^ (r & 7)) << 4));
                ldmx4(ah[i], ad);
                ldmx4(al[i], ad + TILEB);
            }
#pragma unroll
            for (int j = 0; j < 4; j++) {
                int r = wn * 32 + j * 8 + (lane & 7);
                int c = ks * 2 + ((lane >> 3) & 1);
                uint32_t bd = base + (uint32_t)(2 * TILEB + r * 128 + ((c ^ (r & 7)) << 4));
                ldmx2(bh[j], bd);
                ldmx2(bl[j], bd + TILEB);
            }
#pragma unroll
            for (int i = 0; i < 4; i++)
#pragma unroll
                for (int j = 0; j < 4; j++) {
                    mma16816(acc[i][j], ah[i], bh[j]);
                    mma16816(acc[i][j], ah[i], bl[j]);
                    mma16816(acc[i][j], al[i], bh[j]);
                }
        }
        __syncthreads();
        if (tid == 0 && s + NBUF < NSTG) issue(s + NBUF);
    }

    // ---- epilogue 1: fragments -> g_h --------------------------------------
    const int r0 = rowBase + wm * 64, c0 = head * 128 + wn * 32;
#pragma unroll
    for (int i = 0; i < 4; i++)
#pragma unroll
        for (int j = 0; j < 4; j++) {
            int rr = r0 + i * 16 + (lane >> 2);
            int cc = c0 + j * 8 + (lane & 3) * 2;
            float2 v0 = make_float2(acc[i][j][0], acc[i][j][1]);
            float2 v1 = make_float2(acc[i][j][2], acc[i][j][3]);
            *reinterpret_cast<float2*>(&g_h[(size_t)rr * FF + cc]) = v0;
            *reinterpret_cast<float2*>(&g_h[(size_t)(rr + 8) * FF + cc]) = v1;
        }

    // ---- epilogue 2: fused e_src / e_dst -----------------------------------
    float as_[4][2], ad_[4][2];
#pragma unroll
    for (int j = 0; j < 4; j++) {
        int cl = wn * 32 + j * 8 + (lane & 3) * 2;
        as_[j][0] = a_src[head * DD + cl];
        as_[j][1] = a_src[head * DD + cl + 1];
        ad_[j][0] = a_dst[head * DD + cl];
        ad_[j][1] = a_dst[head * DD + cl + 1];
    }
    float es[8], ed[8];
#pragma unroll
    for (int i = 0; i < 4; i++)
#pragma unroll
        for (int sub = 0; sub < 2; sub++) {
            float s_ = 0.f, d_ = 0.f;
#pragma unroll
            for (int j = 0; j < 4; j++) {
                s_ += acc[i][j][sub * 2] * as_[j][0] + acc[i][j][sub * 2 + 1] * as_[j][1];
                d_ += acc[i][j][sub * 2] * ad_[j][0] + acc[i][j][sub * 2 + 1] * ad_[j][1];
            }
            es[i * 2 + sub] = s_;
            ed[i * 2 + sub] = d_;
        }
#pragma unroll
    for (int o = 1; o <= 2; o <<= 1)
#pragma unroll
        for (int t = 0; t < 8; t++) {
            es[t] += __shfl_xor_sync(0xffffffffu, es[t], o);
            ed[t] += __shfl_xor_sync(0xffffffffu, ed[t], o);
        }
    float* e_s = reinterpret_cast<float*>(smc + 1024);        // [128][4]
    float* e_d = reinterpret_cast<float*>(smc + 1024 + 2048); // [128][4]
    __syncthreads();
    if ((lane & 3) == 0) {
#pragma unroll
        for (int i = 0; i < 4; i++)
#pragma unroll
            for (int sub = 0; sub < 2; sub++) {
                int r = wm * 64 + i * 16 + sub * 8 + (lane >> 2);
                e_s[r * 4 + wn] = es[i * 2 + sub];
                e_d[r * 4 + wn] = ed[i * 2 + sub];
            }
    }
    __syncthreads();
    if (tid < 128) {
        float s_ = e_s[tid * 4 + 0] + e_s[tid * 4 + 1] + e_s[tid * 4 + 2] + e_s[tid * 4 + 3];
        float d_ = e_d[tid * 4 + 0] + e_d[tid * 4 + 1] + e_d[tid * 4 + 2] + e_d[tid * 4 + 3];
        g_esrc[(rowBase + tid) * 4 + head] = s_;
        g_edst[(rowBase + tid) * 4 + head] = d_;
    }
}

// ---------------- kernel 3: per (b,h) bitonic sort of valid e_dst -------------
__global__ __launch_bounds__(1024)
void k_sort(const int* __restrict__ mask)
{
    int bh = blockIdx.x;
    int b  = bh >> 2, hh = bh & 3;
    int tid = threadIdx.x;
    __shared__ float key[NN];
    __shared__ int   idx[NN];

    int m = mask[b * NN + tid];
    float e = g_edst[(b * NN + tid) * 4 + hh];
    key[tid] = (m != 0) ? e : FLOATMAX;
    idx[tid] = tid;
    int cnt = __syncthreads_count(m != 0);
    if (tid == 0 && hh == 0) g_nvalid[b] = cnt;

    for (int k = 2; k <= NN; k <<= 1) {
        for (int j = k >> 1; j > 0; j >>= 1) {
            __syncthreads();
            int ixj = tid ^ j;
            if (ixj > tid) {
                bool up = ((tid & k) == 0);
                float ka = key[tid], kb = key[ixj];
                if ((ka > kb) == up) {
                    key[tid] = kb; key[ixj] = ka;
                    int ia = idx[tid]; idx[tid] = idx[ixj]; idx[ixj] = ia;
                }
            }
        }
    }
    __syncthreads();
    g_key [bh * NN + tid] = key[tid];
    g_sidx[bh * NN + tid] = idx[tid];
}

// ---------------- kernel 4a: tile-local prefix scans + hmean partials ---------
__global__ __launch_bounds__(DD)
void k_scanA()
{
    int t  = blockIdx.x;
    int bh = blockIdx.y;
    int b = bh >> 2, hh = bh & 3;
    int d = threadIdx.x;

    __shared__ int   sj [TILE];
    __shared__ float sw1[TILE];
    __shared__ float sw2[TILE];

    int nv = g_nvalid[b];
    if (d < TILE) {
        int k = t * TILE + d;
        sj[d] = g_sidx[bh * NN + k];
        float e = g_key[bh * NN + k];
        bool v = (k < nv);
        sw1[d] = v ? __expf(0.2f * e) : 0.f;
        sw2[d] = v ? __expf(e) : 0.f;
    }
    __syncthreads();

    const float* hb = g_h + ((size_t)b << 10) * FF + hh * DD + d;
    float* P1 = g_p1 + ((size_t)bh * NN + t * TILE) * DD + d;
    float* P2 = g_p2 + ((size_t)bh * NN + t * TILE) * DD + d;

    float acc1 = 0.f, acc2 = 0.f;
    float hv[8];
#pragma unroll
    for (int u = 0; u < 8; u++) hv[u] = hb[(size_t)sj[u] * FF];
    for (int m0 = 0; m0 < TILE; m0 += 8) {
        float cur[8];
#pragma unroll
        for (int u = 0; u < 8; u++) cur[u] = hv[u];
        if (m0 + 8 < TILE) {
#pragma unroll
            for (int u = 0; u < 8; u++) hv[u] = hb[(size_t)sj[m0 + 8 + u] * FF];
        }
#pragma unroll
        for (int u = 0; u < 8; u++) {
            int m = m0 + u;
            acc1 = fmaf(sw1[m], cur[u], acc1);
            acc2 = fmaf(sw2[m], cur[u], acc2);
            P1[(size_t)m * DD] = acc1;
            P2[(size_t)m * DD] = acc2;
        }
    }
    g_t1[(bh * NT + t) * DD + d] = acc1;
    g_t2[(bh * NT + t) * DD + d] = acc2;

    if (d == 0) {
        float s1 = 0.f, s2 = 0.f;
        int base = bh * (NN + 1) + t * TILE;
#pragma unroll 8
        for (int m = 0; m < TILE; m++) {
            s1 += sw1[m]; s2 += sw2[m];
            g_s1[base + m + 1] = s1;
            g_s2[base + m + 1] = s2;
        }
    }

    float m0a = 0.f, m1a = 0.f, m2a = 0.f, m3a = 0.f;
    const float* hj = g_h + (((size_t)b << 10) + t * TILE) * FF + hh * DD + d;
#pragma unroll 8
    for (int j = 0; j < TILE; j += 4) {
        m0a += hj[(size_t)(j + 0) * FF];
        m1a += hj[(size_t)(j + 1) * FF];
        m2a += hj[(size_t)(j + 2) * FF];
        m3a += hj[(size_t)(j + 3) * FF];
    }
    g_hp[(bh * NT + t) * DD + d] = (m0a + m1a) + (m2a + m3a);
}

// ---------------- kernel 4b: tile offsets + scalar fixup + hmean --------------
__global__ __launch_bounds__(DD)
void k_scanB()
{
    int bh = blockIdx.x;
    int d  = threadIdx.x;

    float o1 = 0.f, o2 = 0.f, hm = 0.f;
#pragma unroll
    for (int t = 0; t < NT; t++) {
        g_off1[(bh * (NT + 1) + t) * DD + d] = o1;
        g_off2[(bh * (NT + 1) + t) * DD + d] = o2;
        o1 += g_t1[(bh * NT + t) * DD + d];
        o2 += g_t2[(bh * NT + t) * DD + d];
        hm += g_hp[(bh * NT + t) * DD + d];
    }
    g_off1[(bh * (NT + 1) + NT) * DD + d] = o1;
    g_off2[(bh * (NT + 1) + NT) * DD + d] = o2;
    g_hmean[bh * DD + d] = hm * (1.f / (float)NN);

    __shared__ float so1[NT + 1], so2[NT + 1];
    int base = bh * (NN + 1);
    if (d == 0) {
        float a1 = 0.f, a2 = 0.f;
#pragma unroll
        for (int t = 0; t < NT; t++) {
            so1[t] = a1; so2[t] = a2;
            a1 += g_s1[base + t * TILE + TILE];
            a2 += g_s2[base + t * TILE + TILE];
        }
        so1[NT] = a1; so2[NT] = a2;
        g_s1[base] = 0.f; g_s2[base] = 0.f;
    }
    __syncthreads();
    for (int k = d + 1; k <= NN; k += DD) {
        int t = (k - 1) >> 6;
        g_s1[base + k] += so1[t];
        g_s2[base + k] += so2[t];
    }
}

// ---------------- kernel 5: per-row combine + residual + LayerNorm ------------
__global__ __launch_bounds__(128)
void k_final(const float* __restrict__ x, const int* __restrict__ mask,
             const float* __restrict__ gamma, const float* __restrict__ beta,
             float* __restrict__ out)
{
    int row  = blockIdx.x;
    int b    = row >> 10;
    int tid  = threadIdx.x;
    int warp = tid >> 5;
    int lane = tid & 31;
    __shared__ float yv[FF];
    __shared__ float red[8];

    int nv = g_nvalid[b];
    bool uni = (mask[row] == 0) || (nv == 0);
    int hh = warp;
    int bh = b * 4 + hh;

    float4 xr = *reinterpret_cast<const float4*>(&x[(size_t)row * FF + hh * DD + lane * 4]);
    float4 y;
    if (uni) {
        float4 hm = *reinterpret_cast<const float4*>(&g_hmean[bh * DD + lane * 4]);
        y.x = hm.x + xr.x; y.y = hm.y + xr.y; y.z = hm.z + xr.z; y.w = hm.w + xr.w;
    } else {
        float ei = g_esrc[row * 4 + hh];
        float tt = -ei;
        const float* keys = g_key + bh * NN;
        int lo = 0, hi = nv;
        while (lo < hi) {
            int mid = (lo + hi) >> 1;
            if (keys[mid] <= tt) lo = mid + 1; else hi = mid;
        }
        int k0 = lo;
        int t0 = k0 >> 6, m0 = k0 & 63;
        int tn = nv >> 6, mn = nv & 63;

        float w1 = __expf(0.2f * ei);
        float w2 = __expf(ei);
        float den = w1 * g_s1[bh * (NN + 1) + k0]
                  + w2 * (g_s2[bh * (NN + 1) + nv] - g_s2[bh * (NN + 1) + k0]);
        float inv = 1.0f / den;

        const float4 z4 = make_float4(0.f, 0.f, 0.f, 0.f);
        size_t ob = (size_t)(bh * (NT + 1));
        float4 o1 = *reinterpret_cast<const float4*>(&g_off1[(ob + t0) * DD + lane * 4]);
        float4 o2 = *reinterpret_cast<const float4*>(&g_off2[(ob + t0) * DD + lane * 4]);
        float4 on = *reinterpret_cast<const float4*>(&g_off2[(ob + tn) * DD + lane * 4]);
        float4 l1 = m0 ? *reinterpret_cast<const float4*>(
                        &g_p1[((size_t)bh * NN + k0 - 1) * DD + lane * 4]) : z4;
        float4 l2 = m0 ? *reinterpret_cast<const float4*>(
                        &g_p2[((size_t)bh * NN + k0 - 1) * DD + lane * 4]) : z4;
        float4 ln = mn ? *reinterpret_cast<const float4*>(
                        &g_p2[((size_t)bh * NN + nv - 1) * DD + lane * 4]) : z4;

        float P1x = o1.x + l1.x, P1y = o1.y + l1.y, P1z = o1.z + l1.z, P1w = o1.w + l1.w;
        float Pax = o2.x + l2.x, Pay = o2.y + l2.y, Paz = o2.z + l2.z, Paw = o2.w + l2.w;
        float Pbx = on.x + ln.x, Pby = on.y + ln.y, Pbz = on.z + ln.z, Pbw = on.w + ln.w;

        y.x = (w1 * P1x + w2 * (Pbx - Pax)) * inv + xr.x;
        y.y = (w1 * P1y + w2 * (Pby - Pay)) * inv + xr.y;
        y.z = (w1 * P1z + w2 * (Pbz - Paz)) * inv + xr.z;
        y.w = (w1 * P1w + w2 * (Pbw - Paw)) * inv + xr.w;
    }
    *reinterpret_cast<float4*>(&yv[hh * DD + lane * 4]) = y;
    __syncthreads();

    float s = 0.f;
#pragma unroll
    for (int u = 0; u < 4; u++) s += yv[tid + u * 128];
#pragma unroll
    for (int o = 16; o > 0; o >>= 1) s += __shfl_xor_sync(0xffffffffu, s, o);
    if (lane == 0) red[warp] = s;
    __syncthreads();
    float mu = (red[0] + red[1] + red[2] + red[3]) * (1.0f / (float)FF);

    float q = 0.f;
#pragma unroll
    for (int u = 0; u < 4; u++) {
        float dlt = yv[tid + u * 128] - mu;
        q += dlt * dlt;
    }
#pragma unroll
    for (int o = 16; o > 0; o >>= 1) q += __shfl_xor_sync(0xffffffffu, q, o);
    if (lane == 0) red[4 + warp] = q;
    __syncthreads();
    float var = (red[4] + red[5] + red[6] + red[7]) * (1.0f / (float)FF);
    float rs = rsqrtf(var + LN_EPS);

#pragma unroll
    for (int u = 0; u < 4; u++) {
        int c = tid + u * 128;
        out[(size_t)row * FF + c] = (yv[c] - mu) * rs * gamma[c] + beta[c];
    }
}

// ---------------- launch ------------------------------------------------------
extern "C" void kernel_launch(void* const* d_in, const int* in_sizes, int n_in,
                              void* d_out, int out_size)
{
    const float* x     = (const float*)d_in[0];
    const int*   mask  = (const int*)  d_in[1];
    const float* W     = (const float*)d_in[2];
    const float* a_src = (const float*)d_in[3];
    const float* a_dst = (const float*)d_in[4];
    const float* gamma = (const float*)d_in[5];
    const float* beta  = (const float*)d_in[6];
    float* out = (float*)d_out;

    static int smem_set = 0;
    if (!smem_set) {
        cudaFuncSetAttribute(k_gemm_mma,
                             cudaFuncAttributeMaxDynamicSharedMemorySize, SMEM_GEMM);
        smem_set = 1;
    }

    k_convA<<<(ROWS * FF) / (256 * 8), 256>>>(x);
    k_convB<<<dim3(FF / 64, FF / 64), 256>>>(W);
    k_gemm_mma<<<dim3(FF / 128, ROWS / 128), 256, SMEM_GEMM>>>(a_src, a_dst);
    k_sort <<<BH, NN>>>(mask);
    k_scanA<<<dim3(NT, BH), DD>>>();
    k_scanB<<<BH, DD>>>();
    k_final<<<ROWS, 128>>>(x, mask, gamma, beta, out);
}